// round 1
// baseline (speedup 1.0000x reference)
#include <cuda_runtime.h>
#include <math.h>

#define T_TOK 4096
#define E_DIM 1024
#define B_SZ  4
#define NSTEP 128

// ---------------- persistent device scratch (static, allocation-free) -------
__device__ float g_M[64 * 64];                 // w_fft2 @ w_fft1 (lower-tri 64x64)
__device__ float g_state[B_SZ * 32 * E_DIM];   // carried proc[:,32:,:]
__device__ float g_cn[B_SZ * 64 * E_DIM];      // LN1 output
__device__ float g_res2[B_SZ * 64 * E_DIM];    // fft + chunk residual
__device__ float g_part2[B_SZ * 64 * 8 * 2];   // LN2 partial (sum, sumsq) per e-chunk
__device__ float g_f[B_SZ * 64 * 4096];        // sin(gate)*val
__device__ float g_opart[8 * B_SZ * 64 * E_DIM]; // split-K partials of GEMM2

__device__ __forceinline__ float warp_sum(float v) {
#pragma unroll
    for (int m = 16; m > 0; m >>= 1) v += __shfl_xor_sync(0xffffffffu, v, m);
    return v;
}

// ---------------- init: M = w_fft2 @ w_fft1 ---------------------------------
__global__ void k_init_M(const float* __restrict__ wf1,   // (48,64)
                         const float* __restrict__ wf2) { // (64,48)
    int idx = blockIdx.x * 256 + threadIdx.x;   // 4096 entries
    int t = idx >> 6, tp = idx & 63;
    float s = 0.f;
#pragma unroll 8
    for (int u = 0; u < 48; u++)
        s = fmaf(wf2[t * 48 + u], wf1[u * 64 + tp], s);
    g_M[idx] = s;
}

// ---------------- init: state = x[:, :32, :] --------------------------------
__global__ void k_init_state(const float* __restrict__ x) {
    int idx = (blockIdx.x * 256 + threadIdx.x) * 4;   // < 131072
    int b = idx >> 15;                 // 32*1024 floats per batch
    int r = idx & 32767;
    *(float4*)(g_state + idx) = *(const float4*)(x + ((size_t)b << 22) + r);
}

// ---------------- step kernel 1: LN1 of mixed -> g_cn ------------------------
__global__ __launch_bounds__(256) void k_ln1(const float* __restrict__ x,
                                             const float* __restrict__ w,
                                             const float* __restrict__ bb,
                                             int step) {
    int t = blockIdx.x, b = blockIdx.y, tid = threadIdx.x;
    float4 vv = make_float4(0.f, 0.f, 0.f, 0.f);
    if (t < 32) {
        vv = *(const float4*)(g_state + ((b * 32 + t) << 10) + tid * 4);
    } else {
        int tok = step * 32 + t;
        if (tok < T_TOK)
            vv = *(const float4*)(x + ((size_t)(b * T_TOK + tok) << 10) + tid * 4);
    }
    float s = vv.x + vv.y + vv.z + vv.w;
    float q = vv.x * vv.x + vv.y * vv.y + vv.z * vv.z + vv.w * vv.w;
    __shared__ float rs[8], rq[8];
    __shared__ float smu, srstd;
    s = warp_sum(s);
    q = warp_sum(q);
    int wid = tid >> 5;
    if ((tid & 31) == 0) { rs[wid] = s; rq[wid] = q; }
    __syncthreads();
    if (tid == 0) {
        float S = 0.f, Q = 0.f;
#pragma unroll
        for (int i = 0; i < 8; i++) { S += rs[i]; Q += rq[i]; }
        float mu = S * (1.f / 1024.f);
        float var = Q * (1.f / 1024.f) - mu * mu;
        smu = mu;
        srstd = rsqrtf(var + 1e-5f);
    }
    __syncthreads();
    float mu = smu, rstd = srstd;
    float4 wv = *(const float4*)(w + tid * 4);
    float4 bv = *(const float4*)(bb + tid * 4);
    float4 o;
    o.x = (vv.x - mu) * rstd * wv.x + bv.x;
    o.y = (vv.y - mu) * rstd * wv.y + bv.y;
    o.z = (vv.z - mu) * rstd * wv.z + bv.z;
    o.w = (vv.w - mu) * rstd * wv.w + bv.w;
    *(float4*)(g_cn + ((b * 64 + t) << 10) + tid * 4) = o;
}

// ---------------- step kernel 2: fft = M@cn, res2, LN2 partial stats ---------
__global__ __launch_bounds__(128) void k_fft(const float* __restrict__ x, int step) {
    __shared__ float cns[64][128];
    __shared__ float wsum[4][64], wsq[4][64];
    int chunk = blockIdx.x, b = blockIdx.y;
    int tid = threadIdx.x;
    int e = chunk * 128 + tid;
#pragma unroll 4
    for (int tp = 0; tp < 64; tp++)
        cns[tp][tid] = g_cn[((b * 64 + tp) << 10) + e];
    __syncthreads();
    int w = tid >> 5, lane = tid & 31;
    for (int t = 0; t < 64; t++) {
        const float* Mrow = g_M + t * 64;
        float acc = 0.f;
        for (int tp = 0; tp <= t; tp++)
            acc = fmaf(Mrow[tp], cns[tp][tid], acc);
        int tok = step * 32 + t;
        float cv = (tok < T_TOK) ? x[((size_t)(b * T_TOK + tok) << 10) + e] : 0.f;
        float r = acc + cv;
        g_res2[((b * 64 + t) << 10) + e] = r;
        float s = warp_sum(r);
        float q = warp_sum(r * r);
        if (lane == 0) { wsum[w][t] = s; wsq[w][t] = q; }
    }
    __syncthreads();
    if (tid < 64) {
        float S = wsum[0][tid] + wsum[1][tid] + wsum[2][tid] + wsum[3][tid];
        float Q = wsq[0][tid] + wsq[1][tid] + wsq[2][tid] + wsq[3][tid];
        int base = ((b * 64 + tid) * 8 + chunk) * 2;
        g_part2[base] = S;
        g_part2[base + 1] = Q;
    }
}

// ---------------- step kernel 3: GEMM1 (LN2-normalize fused A-load,
//                  +b_up and sin(gate)*val fused epilogue -> g_f) -------------
// grid (64, 2), block 256. Tile: M=128 rows x (64 gate cols + 64 val cols).
__global__ __launch_bounds__(256) void k_gemm1(const float* __restrict__ w_up,
                                               const float* __restrict__ b_up,
                                               const float* __restrict__ ln2w,
                                               const float* __restrict__ ln2b) {
    __shared__ float As[8][128];
    __shared__ float Bs[8][128];
    __shared__ float s_mu[128], s_rs[128];
    int tid = threadIdx.x;
    int bx = blockIdx.x, by = blockIdx.y;
    if (tid < 128) {
        int gm = by * 128 + tid;
        float S = 0.f, Q = 0.f;
#pragma unroll
        for (int c = 0; c < 8; c++) {
            S += g_part2[gm * 16 + c * 2];
            Q += g_part2[gm * 16 + c * 2 + 1];
        }
        float mu = S * (1.f / 1024.f);
        float var = Q * (1.f / 1024.f) - mu * mu;
        s_mu[tid] = mu;
        s_rs[tid] = rsqrtf(var + 1e-5f);
    }
    __syncthreads();
    int arow = tid >> 1, acol = (tid & 1) * 4;
    const float* Ap = g_res2 + ((by * 128 + arow) << 10);
    int fr = (arow < 64) ? (bx * 64 + arow) : (4096 + bx * 64 + arow - 64);
    const float* Bp = w_up + ((size_t)fr << 10);
    float muA = s_mu[arow], rsA = s_rs[arow];
    int tx = tid & 15, ty = tid >> 4;
    float acc[8][8];
#pragma unroll
    for (int i = 0; i < 8; i++)
#pragma unroll
        for (int j = 0; j < 8; j++) acc[i][j] = 0.f;

    for (int k0 = 0; k0 < 1024; k0 += 8) {
        float4 av = *(const float4*)(Ap + k0 + acol);
        float4 wv = *(const float4*)(ln2w + k0 + acol);
        float4 bv = *(const float4*)(ln2b + k0 + acol);
        As[acol + 0][arow] = (av.x - muA) * rsA * wv.x + bv.x;
        As[acol + 1][arow] = (av.y - muA) * rsA * wv.y + bv.y;
        As[acol + 2][arow] = (av.z - muA) * rsA * wv.z + bv.z;
        As[acol + 3][arow] = (av.w - muA) * rsA * wv.w + bv.w;
        float4 b4 = *(const float4*)(Bp + k0 + acol);
        Bs[acol + 0][arow] = b4.x;
        Bs[acol + 1][arow] = b4.y;
        Bs[acol + 2][arow] = b4.z;
        Bs[acol + 3][arow] = b4.w;
        __syncthreads();
#pragma unroll
        for (int k = 0; k < 8; k++) {
            float af[8], bf[8];
            *(float4*)(af)     = *(const float4*)(&As[k][ty * 4]);
            *(float4*)(af + 4) = *(const float4*)(&As[k][64 + ty * 4]);
            *(float4*)(bf)     = *(const float4*)(&Bs[k][tx * 4]);
            *(float4*)(bf + 4) = *(const float4*)(&Bs[k][64 + tx * 4]);
#pragma unroll
            for (int mi = 0; mi < 8; mi++)
#pragma unroll
                for (int ni = 0; ni < 8; ni++)
                    acc[mi][ni] = fmaf(af[mi], bf[ni], acc[mi][ni]);
        }
        __syncthreads();
    }
    int j0 = bx * 64 + tx * 4;
    float bg[4], bvv[4];
#pragma unroll
    for (int ni = 0; ni < 4; ni++) {
        bg[ni] = b_up[j0 + ni];
        bvv[ni] = b_up[4096 + j0 + ni];
    }
#pragma unroll
    for (int mi = 0; mi < 8; mi++) {
        int r = (mi < 4) ? (ty * 4 + mi) : (64 + ty * 4 + mi - 4);
        int gm = by * 128 + r;
        float* fp = g_f + gm * 4096 + j0;
        float4 o;
        o.x = sinf(acc[mi][0] + bg[0]) * (acc[mi][4] + bvv[0]);
        o.y = sinf(acc[mi][1] + bg[1]) * (acc[mi][5] + bvv[1]);
        o.z = sinf(acc[mi][2] + bg[2]) * (acc[mi][6] + bvv[2]);
        o.w = sinf(acc[mi][3] + bg[3]) * (acc[mi][7] + bvv[3]);
        *(float4*)fp = o;
    }
}

// ---------------- step kernel 4: GEMM2 split-K=8 -> g_opart ------------------
// grid (8, 2, 8), block 256. Tile 128x128, K slice of 512.
__global__ __launch_bounds__(256) void k_gemm2(const float* __restrict__ w_down) {
    __shared__ float As[8][128];
    __shared__ float Bs[8][128];
    int tid = threadIdx.x;
    int bx = blockIdx.x, by = blockIdx.y, bz = blockIdx.z;
    int arow = tid >> 1, acol = (tid & 1) * 4;
    const float* Ap = g_f + (by * 128 + arow) * 4096 + bz * 512;
    int n = bx * 128 + arow;
    const float* Bp = w_down + (size_t)n * 4096 + bz * 512;
    int tx = tid & 15, ty = tid >> 4;
    float acc[8][8];
#pragma unroll
    for (int i = 0; i < 8; i++)
#pragma unroll
        for (int j = 0; j < 8; j++) acc[i][j] = 0.f;

    for (int k0 = 0; k0 < 512; k0 += 8) {
        float4 a4 = *(const float4*)(Ap + k0 + acol);
        As[acol + 0][arow] = a4.x;
        As[acol + 1][arow] = a4.y;
        As[acol + 2][arow] = a4.z;
        As[acol + 3][arow] = a4.w;
        float4 b4 = *(const float4*)(Bp + k0 + acol);
        Bs[acol + 0][arow] = b4.x;
        Bs[acol + 1][arow] = b4.y;
        Bs[acol + 2][arow] = b4.z;
        Bs[acol + 3][arow] = b4.w;
        __syncthreads();
#pragma unroll
        for (int k = 0; k < 8; k++) {
            float af[8], bf[8];
            *(float4*)(af)     = *(const float4*)(&As[k][ty * 4]);
            *(float4*)(af + 4) = *(const float4*)(&As[k][64 + ty * 4]);
            *(float4*)(bf)     = *(const float4*)(&Bs[k][tx * 4]);
            *(float4*)(bf + 4) = *(const float4*)(&Bs[k][64 + tx * 4]);
#pragma unroll
            for (int mi = 0; mi < 8; mi++)
#pragma unroll
                for (int ni = 0; ni < 8; ni++)
                    acc[mi][ni] = fmaf(af[mi], bf[ni], acc[mi][ni]);
        }
        __syncthreads();
    }
#pragma unroll
    for (int mi = 0; mi < 8; mi++) {
        int r = (mi < 4) ? (ty * 4 + mi) : (64 + ty * 4 + mi - 4);
        int gm = by * 128 + r;
        float* op = g_opart + (((bz << 8) + gm) << 10) + bx * 128;
        *(float4*)(op + tx * 4)      = make_float4(acc[mi][0], acc[mi][1], acc[mi][2], acc[mi][3]);
        *(float4*)(op + 64 + tx * 4) = make_float4(acc[mi][4], acc[mi][5], acc[mi][6], acc[mi][7]);
    }
}

// ---------------- step kernel 5: reduce split-K + residual + scatter ---------
__global__ __launch_bounds__(256) void k_fin(const float* __restrict__ b_down,
                                             float* __restrict__ out, int step) {
    int gm = blockIdx.x, tid = threadIdx.x;
    int nn = tid * 4;
    float4 a = *(const float4*)(g_opart + ((size_t)gm << 10) + nn);
#pragma unroll
    for (int s = 1; s < 8; s++) {
        float4 p = *(const float4*)(g_opart + ((size_t)((s << 8) + gm) << 10) + nn);
        a.x += p.x; a.y += p.y; a.z += p.z; a.w += p.w;
    }
    float4 bd = *(const float4*)(b_down + nn);
    float4 r2 = *(const float4*)(g_res2 + ((size_t)gm << 10) + nn);
    a.x += bd.x + r2.x;
    a.y += bd.y + r2.y;
    a.z += bd.z + r2.z;
    a.w += bd.w + r2.w;
    int b = gm >> 6, t = gm & 63;
    float* dst;
    if (t < 32)
        dst = out + ((size_t)(b * T_TOK + step * 32 + t) << 10) + nn;
    else
        dst = g_state + ((b * 32 + (t - 32)) << 10) + nn;
    *(float4*)dst = a;
}

// ---------------- host launcher ----------------------------------------------
extern "C" void kernel_launch(void* const* d_in, const int* in_sizes, int n_in,
                              void* d_out, int out_size) {
    const float* x     = (const float*)d_in[0];
    const float* ln1w  = (const float*)d_in[1];
    const float* ln1b  = (const float*)d_in[2];
    const float* wf1   = (const float*)d_in[3];
    const float* wf2   = (const float*)d_in[4];
    const float* ln2w  = (const float*)d_in[5];
    const float* ln2b  = (const float*)d_in[6];
    const float* w_up  = (const float*)d_in[7];
    const float* b_up  = (const float*)d_in[8];
    const float* w_dn  = (const float*)d_in[9];
    const float* b_dn  = (const float*)d_in[10];
    float* out = (float*)d_out;

    k_init_M<<<16, 256>>>(wf1, wf2);
    k_init_state<<<128, 256>>>(x);

    for (int i = 0; i < NSTEP; i++) {
        k_ln1<<<dim3(64, 4), 256>>>(x, ln1w, ln1b, i);
        k_fft<<<dim3(8, 4), 128>>>(x, i);
        k_gemm1<<<dim3(64, 2), 256>>>(w_up, b_up, ln2w, ln2b);
        k_gemm2<<<dim3(8, 2, 8), 256>>>(w_dn);
        k_fin<<<256, 256>>>(b_dn, out, i);
    }
}

// round 4
// speedup vs baseline: 3.4582x; 3.4582x over previous
#include <cuda_runtime.h>
#include <cuda_bf16.h>
#include <math.h>
#include <stdint.h>

#define T_TOK 4096
#define E_DIM 1024
#define B_SZ  4
#define NSTEP 128

// ---------------- persistent device scratch ---------------------------------
__device__ float g_M[64 * 64];
__device__ float g_state[B_SZ * 32 * E_DIM];
__device__ float g_cn[B_SZ * 64 * E_DIM];
__device__ float g_res2[B_SZ * 64 * E_DIM];
__device__ __nv_bfloat16 g_ahi[256 * 1024];     // LN2 activations hi
__device__ __nv_bfloat16 g_alo[256 * 1024];     // lo residual
__device__ __nv_bfloat16 g_fhi[256 * 4096];     // sin(gate)*val hi
__device__ __nv_bfloat16 g_flo[256 * 4096];
__device__ __nv_bfloat16 g_wuphi[8192 * 1024];  // pair-interleaved w_up hi
__device__ __nv_bfloat16 g_wuplo[8192 * 1024];
__device__ __nv_bfloat16 g_wdnhi[1024 * 4096];
__device__ __nv_bfloat16 g_wdnlo[1024 * 4096];
__device__ float g_opart[8 * 256 * 1024];

// ---------------- helpers ----------------------------------------------------
__device__ __forceinline__ uint32_t smem_u32(const void* p) {
    uint32_t a;
    asm("{ .reg .u64 t; cvta.to.shared.u64 t, %1; cvt.u32.u64 %0, t; }" : "=r"(a) : "l"(p));
    return a;
}
#define CP_ASYNC16(dst, src) \
    asm volatile("cp.async.cg.shared.global [%0], [%1], 16;" :: "r"(dst), "l"(src))
#define CP_COMMIT() asm volatile("cp.async.commit_group;" ::: "memory")
#define CP_WAIT1()  asm volatile("cp.async.wait_group 1;" ::: "memory")

__device__ __forceinline__ float warp_sum(float v) {
#pragma unroll
    for (int m = 16; m > 0; m >>= 1) v += __shfl_xor_sync(0xffffffffu, v, m);
    return v;
}

// ---------------- init kernels -----------------------------------------------
__global__ void k_init_M(const float* __restrict__ wf1, const float* __restrict__ wf2) {
    int idx = blockIdx.x * 256 + threadIdx.x;
    int t = idx >> 6, tp = idx & 63;
    float s = 0.f;
#pragma unroll 8
    for (int u = 0; u < 48; u++) s = fmaf(wf2[t * 48 + u], wf1[u * 64 + tp], s);
    g_M[idx] = s;
}
__global__ void k_init_state(const float* __restrict__ x) {
    int idx = (blockIdx.x * 256 + threadIdx.x) * 4;
    int b = idx >> 15, r = idx & 32767;
    *(float4*)(g_state + idx) = *(const float4*)(x + ((size_t)b << 22) + r);
}
// pair-interleave permutation: dst row n (8192): tile nt=n>>7, i=n&127:
//   i even -> gate row nt*64 + i/2 ; i odd -> val row 4096 + nt*64 + i/2
__global__ void k_conv_wup(const float* __restrict__ w) {
    int n = blockIdx.x, tid = threadIdx.x;
    int nt = n >> 7, i = n & 127;
    int src = (i & 1) ? (4096 + nt * 64 + (i >> 1)) : (nt * 64 + (i >> 1));
    const float* sp = w + ((size_t)src << 10);
    int c = tid * 4;
    float4 v = *(const float4*)(sp + c);
    __nv_bfloat16 h0 = __float2bfloat16(v.x), h1 = __float2bfloat16(v.y);
    __nv_bfloat16 h2 = __float2bfloat16(v.z), h3 = __float2bfloat16(v.w);
    __nv_bfloat16 l0 = __float2bfloat16(v.x - __bfloat162float(h0));
    __nv_bfloat16 l1 = __float2bfloat16(v.y - __bfloat162float(h1));
    __nv_bfloat16 l2 = __float2bfloat16(v.z - __bfloat162float(h2));
    __nv_bfloat16 l3 = __float2bfloat16(v.w - __bfloat162float(h3));
    size_t o = ((size_t)n << 10) + c;
    *(__nv_bfloat162*)(g_wuphi + o) = __halves2bfloat162(h0, h1);
    *(__nv_bfloat162*)(g_wuphi + o + 2) = __halves2bfloat162(h2, h3);
    *(__nv_bfloat162*)(g_wuplo + o) = __halves2bfloat162(l0, l1);
    *(__nv_bfloat162*)(g_wuplo + o + 2) = __halves2bfloat162(l2, l3);
}
__global__ void k_conv_wdn(const float* __restrict__ w) {
    int e = blockIdx.x, tid = threadIdx.x;
    const float* sp = w + (size_t)e * 4096;
#pragma unroll
    for (int j = 0; j < 4; j++) {
        int c = (j * 256 + tid) * 4;
        float4 v = *(const float4*)(sp + c);
        __nv_bfloat16 h0 = __float2bfloat16(v.x), h1 = __float2bfloat16(v.y);
        __nv_bfloat16 h2 = __float2bfloat16(v.z), h3 = __float2bfloat16(v.w);
        __nv_bfloat16 l0 = __float2bfloat16(v.x - __bfloat162float(h0));
        __nv_bfloat16 l1 = __float2bfloat16(v.y - __bfloat162float(h1));
        __nv_bfloat16 l2 = __float2bfloat16(v.z - __bfloat162float(h2));
        __nv_bfloat16 l3 = __float2bfloat16(v.w - __bfloat162float(h3));
        size_t o = (size_t)e * 4096 + c;
        *(__nv_bfloat162*)(g_wdnhi + o) = __halves2bfloat162(h0, h1);
        *(__nv_bfloat162*)(g_wdnhi + o + 2) = __halves2bfloat162(h2, h3);
        *(__nv_bfloat162*)(g_wdnlo + o) = __halves2bfloat162(l0, l1);
        *(__nv_bfloat162*)(g_wdnlo + o + 2) = __halves2bfloat162(l2, l3);
    }
}

// ---------------- step kernel 1: LN1 -> g_cn ---------------------------------
__global__ __launch_bounds__(256) void k_ln1(const float* __restrict__ x,
                                             const float* __restrict__ w,
                                             const float* __restrict__ bb, int step) {
    int t = blockIdx.x, b = blockIdx.y, tid = threadIdx.x;
    float4 vv = make_float4(0.f, 0.f, 0.f, 0.f);
    if (t < 32) {
        vv = *(const float4*)(g_state + ((b * 32 + t) << 10) + tid * 4);
    } else {
        int tok = step * 32 + t;
        if (tok < T_TOK)
            vv = *(const float4*)(x + ((size_t)(b * T_TOK + tok) << 10) + tid * 4);
    }
    float s = vv.x + vv.y + vv.z + vv.w;
    float q = vv.x * vv.x + vv.y * vv.y + vv.z * vv.z + vv.w * vv.w;
    __shared__ float rs[8], rq[8], smu, srstd;
    s = warp_sum(s); q = warp_sum(q);
    int wid = tid >> 5;
    if ((tid & 31) == 0) { rs[wid] = s; rq[wid] = q; }
    __syncthreads();
    if (tid == 0) {
        float S = 0.f, Q = 0.f;
#pragma unroll
        for (int i = 0; i < 8; i++) { S += rs[i]; Q += rq[i]; }
        float mu = S * (1.f / 1024.f);
        smu = mu;
        srstd = rsqrtf(Q * (1.f / 1024.f) - mu * mu + 1e-5f);
    }
    __syncthreads();
    float mu = smu, rstd = srstd;
    float4 wv = *(const float4*)(w + tid * 4);
    float4 bv = *(const float4*)(bb + tid * 4);
    float4 o;
    o.x = (vv.x - mu) * rstd * wv.x + bv.x;
    o.y = (vv.y - mu) * rstd * wv.y + bv.y;
    o.z = (vv.z - mu) * rstd * wv.z + bv.z;
    o.w = (vv.w - mu) * rstd * wv.w + bv.w;
    *(float4*)(g_cn + ((b * 64 + t) << 10) + tid * 4) = o;
}

// ---------------- step kernel 2: fft + res2 + LN2 + bf16-split ---------------
__global__ __launch_bounds__(256) void k_fft(const float* __restrict__ x,
                                             const float* __restrict__ ln2w,
                                             const float* __restrict__ ln2b, int step) {
    int t = blockIdx.x, b = blockIdx.y, tid = threadIdx.x;
    __shared__ float Mrow[64];
    __shared__ float rs[8], rq[8], smu, srstd;
    if (tid < 64) Mrow[tid] = g_M[t * 64 + tid];
    __syncthreads();
    int e0 = tid * 4;
    float4 acc = make_float4(0.f, 0.f, 0.f, 0.f);
    for (int tp = 0; tp <= t; tp++) {
        float m = Mrow[tp];
        float4 c = *(const float4*)(g_cn + ((b * 64 + tp) << 10) + e0);
        acc.x = fmaf(m, c.x, acc.x);
        acc.y = fmaf(m, c.y, acc.y);
        acc.z = fmaf(m, c.z, acc.z);
        acc.w = fmaf(m, c.w, acc.w);
    }
    int tok = step * 32 + t;
    if (tok < T_TOK) {
        float4 cv = *(const float4*)(x + ((size_t)(b * T_TOK + tok) << 10) + e0);
        acc.x += cv.x; acc.y += cv.y; acc.z += cv.z; acc.w += cv.w;
    }
    int gm = b * 64 + t;
    *(float4*)(g_res2 + ((size_t)gm << 10) + e0) = acc;
    float s = acc.x + acc.y + acc.z + acc.w;
    float q = acc.x * acc.x + acc.y * acc.y + acc.z * acc.z + acc.w * acc.w;
    s = warp_sum(s); q = warp_sum(q);
    int wid = tid >> 5;
    if ((tid & 31) == 0) { rs[wid] = s; rq[wid] = q; }
    __syncthreads();
    if (tid == 0) {
        float S = 0.f, Q = 0.f;
#pragma unroll
        for (int i = 0; i < 8; i++) { S += rs[i]; Q += rq[i]; }
        float mu = S * (1.f / 1024.f);
        smu = mu;
        srstd = rsqrtf(Q * (1.f / 1024.f) - mu * mu + 1e-5f);
    }
    __syncthreads();
    float mu = smu, rstd = srstd;
    float4 wv = *(const float4*)(ln2w + e0);
    float4 bv = *(const float4*)(ln2b + e0);
    float a0 = (acc.x - mu) * rstd * wv.x + bv.x;
    float a1 = (acc.y - mu) * rstd * wv.y + bv.y;
    float a2 = (acc.z - mu) * rstd * wv.z + bv.z;
    float a3 = (acc.w - mu) * rstd * wv.w + bv.w;
    __nv_bfloat16 h0 = __float2bfloat16(a0), h1 = __float2bfloat16(a1);
    __nv_bfloat16 h2 = __float2bfloat16(a2), h3 = __float2bfloat16(a3);
    __nv_bfloat16 l0 = __float2bfloat16(a0 - __bfloat162float(h0));
    __nv_bfloat16 l1 = __float2bfloat16(a1 - __bfloat162float(h1));
    __nv_bfloat16 l2 = __float2bfloat16(a2 - __bfloat162float(h2));
    __nv_bfloat16 l3 = __float2bfloat16(a3 - __bfloat162float(h3));
    size_t o = ((size_t)gm << 10) + e0;
    *(__nv_bfloat162*)(g_ahi + o) = __halves2bfloat162(h0, h1);
    *(__nv_bfloat162*)(g_ahi + o + 2) = __halves2bfloat162(h2, h3);
    *(__nv_bfloat162*)(g_alo + o) = __halves2bfloat162(l0, l1);
    *(__nv_bfloat162*)(g_alo + o + 2) = __halves2bfloat162(l2, l3);
}

// ---------------- GEMM core (mma.sync bf16) ----------------------------------
// tile 128x128, BK=64, 8 warps (warp tile 64x32), 2-stage cp.async pipeline
#define PITCH 72                   // 64 + 8 pad elems (144B rows; ldmatrix conflict-free)
#define ATILE_B (128 * PITCH * 2)  // 18432
#define STG (2 * ATILE_B)          // 36864 per stage (A + B)
#define SMEM_TOT (2 * STG)         // 73728

__device__ __forceinline__ void load_stage(uint32_t sbase,
                                           const __nv_bfloat16* __restrict__ A,
                                           const __nv_bfloat16* __restrict__ B,
                                           int m0, int n0, int k0,
                                           int ap, int bp, int tid) {
#pragma unroll
    for (int i = 0; i < 4; i++) {
        int u = i * 256 + tid;
        int row = u >> 3, c16 = u & 7;
        const void* src = A + (size_t)(m0 + row) * ap + k0 + c16 * 8;
        CP_ASYNC16(sbase + (row * PITCH + c16 * 8) * 2, src);
    }
#pragma unroll
    for (int i = 0; i < 4; i++) {
        int u = i * 256 + tid;
        int row = u >> 3, c16 = u & 7;
        const void* src = B + (size_t)(n0 + row) * bp + k0 + c16 * 8;
        CP_ASYNC16(sbase + ATILE_B + (row * PITCH + c16 * 8) * 2, src);
    }
}

__device__ __forceinline__ void compute_stage(uint32_t sA, uint32_t sB,
                                              int wm, int wn, int lane,
                                              float acc[4][4][4]) {
#pragma unroll
    for (int kk = 0; kk < 4; kk++) {
        uint32_t a[4][4];
#pragma unroll
        for (int mt = 0; mt < 4; mt++) {
            uint32_t ad = sA + ((wm * 64 + mt * 16 + (lane & 15)) * PITCH
                                + kk * 16 + (lane >> 4) * 8) * 2;
            asm volatile("ldmatrix.sync.aligned.m8n8.x4.shared.b16 {%0,%1,%2,%3}, [%4];"
                : "=r"(a[mt][0]), "=r"(a[mt][1]), "=r"(a[mt][2]), "=r"(a[mt][3]) : "r"(ad));
        }
        uint32_t b[2][4];
#pragma unroll
        for (int nb = 0; nb < 2; nb++) {
            uint32_t bd = sB + ((wn * 32 + nb * 16 + (lane & 15)) * PITCH
                                + kk * 16 + (lane >> 4) * 8) * 2;
            asm volatile("ldmatrix.sync.aligned.m8n8.x4.shared.b16 {%0,%1,%2,%3}, [%4];"
                : "=r"(b[nb][0]), "=r"(b[nb][1]), "=r"(b[nb][2]), "=r"(b[nb][3]) : "r"(bd));
        }
#pragma unroll
        for (int mt = 0; mt < 4; mt++)
#pragma unroll
            for (int nt = 0; nt < 4; nt++) {
                uint32_t b0 = b[nt >> 1][nt & 1], b1 = b[nt >> 1][2 + (nt & 1)];
                asm volatile(
                    "mma.sync.aligned.m16n8k16.row.col.f32.bf16.bf16.f32 "
                    "{%0,%1,%2,%3}, {%4,%5,%6,%7}, {%8,%9}, {%0,%1,%2,%3};"
                    : "+f"(acc[mt][nt][0]), "+f"(acc[mt][nt][1]),
                      "+f"(acc[mt][nt][2]), "+f"(acc[mt][nt][3])
                    : "r"(a[mt][0]), "r"(a[mt][1]), "r"(a[mt][2]), "r"(a[mt][3]),
                      "r"(b0), "r"(b1));
            }
    }
}

// ---------------- GEMM1: f = sin(gate+bg)*(val+bv), write bf16 hi/lo ---------
// grid (64, 2), block 256
__global__ __launch_bounds__(256) void k_gemm1(const float* __restrict__ b_up) {
    extern __shared__ char smem[];
    uint32_t sb = smem_u32(smem);
    int tid = threadIdx.x, lane = tid & 31, wid = tid >> 5;
    int wm = wid & 1, wn = wid >> 1;
    int bx = blockIdx.x, by = blockIdx.y;
    float acc[4][4][4];
#pragma unroll
    for (int i = 0; i < 4; i++)
#pragma unroll
        for (int j = 0; j < 4; j++)
#pragma unroll
            for (int k = 0; k < 4; k++) acc[i][j][k] = 0.f;

    const int C = 48;   // 3 phases x 16 chunks of 64
    {
        load_stage(sb, g_ahi, g_wuphi, by * 128, bx * 128, 0, 1024, 1024, tid);
        CP_COMMIT();
    }
    for (int c = 0; c < C; c++) {
        if (c + 1 < C) {
            int cn = c + 1;
            int p = cn >> 4, j = cn & 15;
            const __nv_bfloat16* A = (p == 1) ? g_alo : g_ahi;
            const __nv_bfloat16* B = (p == 2) ? g_wuplo : g_wuphi;
            load_stage(sb + (cn & 1) * STG, A, B, by * 128, bx * 128, j * 64, 1024, 1024, tid);
        }
        CP_COMMIT();
        CP_WAIT1();
        __syncthreads();
        uint32_t st = sb + (c & 1) * STG;
        compute_stage(st, st + ATILE_B, wm, wn, lane, acc);
        __syncthreads();
    }

#pragma unroll
    for (int mt = 0; mt < 4; mt++) {
        int r0 = by * 128 + wm * 64 + mt * 16 + (lane >> 2);
#pragma unroll
        for (int nt = 0; nt < 4; nt++) {
            int fc = bx * 64 + wn * 16 + nt * 4 + (lane & 3);
            float bg = b_up[fc], bv = b_up[4096 + fc];
            float f0 = sinf(acc[mt][nt][0] + bg) * (acc[mt][nt][1] + bv);
            float f1 = sinf(acc[mt][nt][2] + bg) * (acc[mt][nt][3] + bv);
            size_t o0 = (size_t)r0 * 4096 + fc;
            size_t o1 = o0 + (size_t)8 * 4096;
            __nv_bfloat16 h0 = __float2bfloat16(f0);
            g_fhi[o0] = h0;
            g_flo[o0] = __float2bfloat16(f0 - __bfloat162float(h0));
            __nv_bfloat16 h1 = __float2bfloat16(f1);
            g_fhi[o1] = h1;
            g_flo[o1] = __float2bfloat16(f1 - __bfloat162float(h1));
        }
    }
}

// ---------------- GEMM2: split-K=8 -> g_opart --------------------------------
// grid (8, 2, 8), block 256
__global__ __launch_bounds__(256) void k_gemm2() {
    extern __shared__ char smem[];
    uint32_t sb = smem_u32(smem);
    int tid = threadIdx.x, lane = tid & 31, wid = tid >> 5;
    int wm = wid & 1, wn = wid >> 1;
    int bx = blockIdx.x, by = blockIdx.y, bz = blockIdx.z;
    float acc[4][4][4];
#pragma unroll
    for (int i = 0; i < 4; i++)
#pragma unroll
        for (int j = 0; j < 4; j++)
#pragma unroll
            for (int k = 0; k < 4; k++) acc[i][j][k] = 0.f;

    const int C = 24;   // 3 phases x 8 chunks of 64
    {
        load_stage(sb, g_fhi, g_wdnhi, by * 128, bx * 128, bz * 512, 4096, 4096, tid);
        CP_COMMIT();
    }
    for (int c = 0; c < C; c++) {
        if (c + 1 < C) {
            int cn = c + 1;
            int p = cn >> 3, j = cn & 7;
            const __nv_bfloat16* A = (p == 1) ? g_flo : g_fhi;
            const __nv_bfloat16* B = (p == 2) ? g_wdnlo : g_wdnhi;
            load_stage(sb + (cn & 1) * STG, A, B, by * 128, bx * 128,
                       bz * 512 + j * 64, 4096, 4096, tid);
        }
        CP_COMMIT();
        CP_WAIT1();
        __syncthreads();
        uint32_t st = sb + (c & 1) * STG;
        compute_stage(st, st + ATILE_B, wm, wn, lane, acc);
        __syncthreads();
    }

#pragma unroll
    for (int mt = 0; mt < 4; mt++) {
        int r0 = by * 128 + wm * 64 + mt * 16 + (lane >> 2);
#pragma unroll
        for (int nt = 0; nt < 4; nt++) {
            int col = bx * 128 + wn * 32 + nt * 8 + (lane & 3) * 2;
            float* op = g_opart + ((size_t)(bz * 256) + r0) * 1024 + col;
            *(float2*)op = make_float2(acc[mt][nt][0], acc[mt][nt][1]);
            *(float2*)(op + (size_t)8 * 1024) = make_float2(acc[mt][nt][2], acc[mt][nt][3]);
        }
    }
}

// ---------------- step kernel 5: reduce + residual + scatter -----------------
__global__ __launch_bounds__(256) void k_fin(const float* __restrict__ b_down,
                                             float* __restrict__ out, int step) {
    int gm = blockIdx.x, tid = threadIdx.x;
    int nn = tid * 4;
    float4 a = *(const float4*)(g_opart + ((size_t)gm << 10) + nn);
#pragma unroll
    for (int s = 1; s < 8; s++) {
        float4 p = *(const float4*)(g_opart + ((size_t)((s << 8) + gm) << 10) + nn);
        a.x += p.x; a.y += p.y; a.z += p.z; a.w += p.w;
    }
    float4 bd = *(const float4*)(b_down + nn);
    float4 r2 = *(const float4*)(g_res2 + ((size_t)gm << 10) + nn);
    a.x += bd.x + r2.x; a.y += bd.y + r2.y; a.z += bd.z + r2.z; a.w += bd.w + r2.w;
    int b = gm >> 6, t = gm & 63;
    float* dst = (t < 32)
        ? out + ((size_t)(b * T_TOK + step * 32 + t) << 10) + nn
        : g_state + ((b * 32 + (t - 32)) << 10) + nn;
    *(float4*)dst = a;
}

// ---------------- host launcher ----------------------------------------------
extern "C" void kernel_launch(void* const* d_in, const int* in_sizes, int n_in,
                              void* d_out, int out_size) {
    const float* x    = (const float*)d_in[0];
    const float* ln1w = (const float*)d_in[1];
    const float* ln1b = (const float*)d_in[2];
    const float* wf1  = (const float*)d_in[3];
    const float* wf2  = (const float*)d_in[4];
    const float* ln2w = (const float*)d_in[5];
    const float* ln2b = (const float*)d_in[6];
    const float* w_up = (const float*)d_in[7];
    const float* b_up = (const float*)d_in[8];
    const float* w_dn = (const float*)d_in[9];
    const float* b_dn = (const float*)d_in[10];
    float* out = (float*)d_out;

    static int configured = 0;
    cudaFuncSetAttribute(k_gemm1, cudaFuncAttributeMaxDynamicSharedMemorySize, SMEM_TOT);
    cudaFuncSetAttribute(k_gemm2, cudaFuncAttributeMaxDynamicSharedMemorySize, SMEM_TOT);
    (void)configured;

    k_init_M<<<16, 256>>>(wf1, wf2);
    k_init_state<<<128, 256>>>(x);
    k_conv_wup<<<8192, 256>>>(w_up);
    k_conv_wdn<<<1024, 256>>>(w_dn);

    for (int i = 0; i < NSTEP; i++) {
        k_ln1<<<dim3(64, 4), 256>>>(x, ln1w, ln1b, i);
        k_fft<<<dim3(64, 4), 256>>>(x, ln2w, ln2b, i);
        k_gemm1<<<dim3(64, 2), 256, SMEM_TOT>>>(b_up);
        k_gemm2<<<dim3(8, 2, 8), 256, SMEM_TOT>>>();
        k_fin<<<256, 256>>>(b_dn, out, i);
    }
}

// round 6
// speedup vs baseline: 3.4711x; 1.0037x over previous
#include <cuda_runtime.h>
#include <cuda_bf16.h>
#include <math.h>
#include <stdint.h>

#define T_TOK 4096
#define E_DIM 1024
#define B_SZ  4
#define NSTEP 128

// ---------------- persistent device scratch ---------------------------------
__device__ float g_M[64 * 64];
__device__ float g_state[B_SZ * 32 * E_DIM];
__device__ float g_cn[B_SZ * 64 * E_DIM];
__device__ float g_res2[B_SZ * 64 * E_DIM];
__device__ __nv_bfloat16 g_ahi[256 * 1024];     // LN2 activations hi
__device__ __nv_bfloat16 g_alo[256 * 1024];     // lo residual
__device__ __nv_bfloat16 g_fhi[256 * 4096];     // sin(gate)*val hi
__device__ __nv_bfloat16 g_flo[256 * 4096];
__device__ __nv_bfloat16 g_wuphi[8192 * 1024];  // pair-interleaved w_up hi
__device__ __nv_bfloat16 g_wuplo[8192 * 1024];
__device__ __nv_bfloat16 g_wdnhi[1024 * 4096];
__device__ __nv_bfloat16 g_wdnlo[1024 * 4096];
__device__ float g_opart[8 * 256 * 1024];

// ---------------- helpers ----------------------------------------------------
__device__ __forceinline__ uint32_t smem_u32(const void* p) {
    uint32_t a;
    asm("{ .reg .u64 t; cvta.to.shared.u64 t, %1; cvt.u32.u64 %0, t; }" : "=r"(a) : "l"(p));
    return a;
}
#define CP_ASYNC16(dst, src) \
    asm volatile("cp.async.cg.shared.global [%0], [%1], 16;" :: "r"(dst), "l"(src))
#define CP_COMMIT() asm volatile("cp.async.commit_group;" ::: "memory")
#define CP_WAIT1()  asm volatile("cp.async.wait_group 1;" ::: "memory")

__device__ __forceinline__ float warp_sum(float v) {
#pragma unroll
    for (int m = 16; m > 0; m >>= 1) v += __shfl_xor_sync(0xffffffffu, v, m);
    return v;
}

// ---------------- init kernels -----------------------------------------------
__global__ void k_init_M(const float* __restrict__ wf1, const float* __restrict__ wf2) {
    int idx = blockIdx.x * 256 + threadIdx.x;
    int t = idx >> 6, tp = idx & 63;
    float s = 0.f;
#pragma unroll 8
    for (int u = 0; u < 48; u++) s = fmaf(wf2[t * 48 + u], wf1[u * 64 + tp], s);
    g_M[idx] = s;
}
__global__ void k_init_state(const float* __restrict__ x) {
    int idx = (blockIdx.x * 256 + threadIdx.x) * 4;
    int b = idx >> 15, r = idx & 32767;
    *(float4*)(g_state + idx) = *(const float4*)(x + ((size_t)b << 22) + r);
}
// pair-interleave permutation: dst row n (8192): tile nt=n>>7, i=n&127:
//   i even -> gate row nt*64 + i/2 ; i odd -> val row 4096 + nt*64 + i/2
__global__ void k_conv_wup(const float* __restrict__ w) {
    int n = blockIdx.x, tid = threadIdx.x;
    int nt = n >> 7, i = n & 127;
    int src = (i & 1) ? (4096 + nt * 64 + (i >> 1)) : (nt * 64 + (i >> 1));
    const float* sp = w + ((size_t)src << 10);
    int c = tid * 4;
    float4 v = *(const float4*)(sp + c);
    __nv_bfloat16 h0 = __float2bfloat16(v.x), h1 = __float2bfloat16(v.y);
    __nv_bfloat16 h2 = __float2bfloat16(v.z), h3 = __float2bfloat16(v.w);
    __nv_bfloat16 l0 = __float2bfloat16(v.x - __bfloat162float(h0));
    __nv_bfloat16 l1 = __float2bfloat16(v.y - __bfloat162float(h1));
    __nv_bfloat16 l2 = __float2bfloat16(v.z - __bfloat162float(h2));
    __nv_bfloat16 l3 = __float2bfloat16(v.w - __bfloat162float(h3));
    size_t o = ((size_t)n << 10) + c;
    *(__nv_bfloat162*)(g_wuphi + o) = __halves2bfloat162(h0, h1);
    *(__nv_bfloat162*)(g_wuphi + o + 2) = __halves2bfloat162(h2, h3);
    *(__nv_bfloat162*)(g_wuplo + o) = __halves2bfloat162(l0, l1);
    *(__nv_bfloat162*)(g_wuplo + o + 2) = __halves2bfloat162(l2, l3);
}
__global__ void k_conv_wdn(const float* __restrict__ w) {
    int e = blockIdx.x, tid = threadIdx.x;
    const float* sp = w + (size_t)e * 4096;
#pragma unroll
    for (int j = 0; j < 4; j++) {
        int c = (j * 256 + tid) * 4;
        float4 v = *(const float4*)(sp + c);
        __nv_bfloat16 h0 = __float2bfloat16(v.x), h1 = __float2bfloat16(v.y);
        __nv_bfloat16 h2 = __float2bfloat16(v.z), h3 = __float2bfloat16(v.w);
        __nv_bfloat16 l0 = __float2bfloat16(v.x - __bfloat162float(h0));
        __nv_bfloat16 l1 = __float2bfloat16(v.y - __bfloat162float(h1));
        __nv_bfloat16 l2 = __float2bfloat16(v.z - __bfloat162float(h2));
        __nv_bfloat16 l3 = __float2bfloat16(v.w - __bfloat162float(h3));
        size_t o = (size_t)e * 4096 + c;
        *(__nv_bfloat162*)(g_wdnhi + o) = __halves2bfloat162(h0, h1);
        *(__nv_bfloat162*)(g_wdnhi + o + 2) = __halves2bfloat162(h2, h3);
        *(__nv_bfloat162*)(g_wdnlo + o) = __halves2bfloat162(l0, l1);
        *(__nv_bfloat162*)(g_wdnlo + o + 2) = __halves2bfloat162(l2, l3);
    }
}

// ---------------- step kernel 1: LN1 -> g_cn ---------------------------------
__global__ __launch_bounds__(256) void k_ln1(const float* __restrict__ x,
                                             const float* __restrict__ w,
                                             const float* __restrict__ bb, int step) {
    int t = blockIdx.x, b = blockIdx.y, tid = threadIdx.x;
    float4 vv = make_float4(0.f, 0.f, 0.f, 0.f);
    if (t < 32) {
        vv = *(const float4*)(g_state + ((b * 32 + t) << 10) + tid * 4);
    } else {
        int tok = step * 32 + t;
        if (tok < T_TOK)
            vv = *(const float4*)(x + ((size_t)(b * T_TOK + tok) << 10) + tid * 4);
    }
    float s = vv.x + vv.y + vv.z + vv.w;
    float q = vv.x * vv.x + vv.y * vv.y + vv.z * vv.z + vv.w * vv.w;
    __shared__ float rs[8], rq[8], smu, srstd;
    s = warp_sum(s); q = warp_sum(q);
    int wid = tid >> 5;
    if ((tid & 31) == 0) { rs[wid] = s; rq[wid] = q; }
    __syncthreads();
    if (tid == 0) {
        float S = 0.f, Q = 0.f;
#pragma unroll
        for (int i = 0; i < 8; i++) { S += rs[i]; Q += rq[i]; }
        float mu = S * (1.f / 1024.f);
        smu = mu;
        srstd = rsqrtf(Q * (1.f / 1024.f) - mu * mu + 1e-5f);
    }
    __syncthreads();
    float mu = smu, rstd = srstd;
    float4 wv = *(const float4*)(w + tid * 4);
    float4 bv = *(const float4*)(bb + tid * 4);
    float4 o;
    o.x = (vv.x - mu) * rstd * wv.x + bv.x;
    o.y = (vv.y - mu) * rstd * wv.y + bv.y;
    o.z = (vv.z - mu) * rstd * wv.z + bv.z;
    o.w = (vv.w - mu) * rstd * wv.w + bv.w;
    *(float4*)(g_cn + ((b * 64 + t) << 10) + tid * 4) = o;
}

// ---------------- step kernel 2: fft + res2 + LN2 + bf16-split ---------------
__global__ __launch_bounds__(256) void k_fft(const float* __restrict__ x,
                                             const float* __restrict__ ln2w,
                                             const float* __restrict__ ln2b, int step) {
    int t = blockIdx.x, b = blockIdx.y, tid = threadIdx.x;
    __shared__ float Mrow[64];
    __shared__ float rs[8], rq[8], smu, srstd;
    if (tid < 64) Mrow[tid] = g_M[t * 64 + tid];
    __syncthreads();
    int e0 = tid * 4;
    float4 acc = make_float4(0.f, 0.f, 0.f, 0.f);
    for (int tp = 0; tp <= t; tp++) {
        float m = Mrow[tp];
        float4 c = *(const float4*)(g_cn + ((b * 64 + tp) << 10) + e0);
        acc.x = fmaf(m, c.x, acc.x);
        acc.y = fmaf(m, c.y, acc.y);
        acc.z = fmaf(m, c.z, acc.z);
        acc.w = fmaf(m, c.w, acc.w);
    }
    int tok = step * 32 + t;
    if (tok < T_TOK) {
        float4 cv = *(const float4*)(x + ((size_t)(b * T_TOK + tok) << 10) + e0);
        acc.x += cv.x; acc.y += cv.y; acc.z += cv.z; acc.w += cv.w;
    }
    int gm = b * 64 + t;
    *(float4*)(g_res2 + ((size_t)gm << 10) + e0) = acc;
    float s = acc.x + acc.y + acc.z + acc.w;
    float q = acc.x * acc.x + acc.y * acc.y + acc.z * acc.z + acc.w * acc.w;
    s = warp_sum(s); q = warp_sum(q);
    int wid = tid >> 5;
    if ((tid & 31) == 0) { rs[wid] = s; rq[wid] = q; }
    __syncthreads();
    if (tid == 0) {
        float S = 0.f, Q = 0.f;
#pragma unroll
        for (int i = 0; i < 8; i++) { S += rs[i]; Q += rq[i]; }
        float mu = S * (1.f / 1024.f);
        smu = mu;
        srstd = rsqrtf(Q * (1.f / 1024.f) - mu * mu + 1e-5f);
    }
    __syncthreads();
    float mu = smu, rstd = srstd;
    float4 wv = *(const float4*)(ln2w + e0);
    float4 bv = *(const float4*)(ln2b + e0);
    float a0 = (acc.x - mu) * rstd * wv.x + bv.x;
    float a1 = (acc.y - mu) * rstd * wv.y + bv.y;
    float a2 = (acc.z - mu) * rstd * wv.z + bv.z;
    float a3 = (acc.w - mu) * rstd * wv.w + bv.w;
    __nv_bfloat16 h0 = __float2bfloat16(a0), h1 = __float2bfloat16(a1);
    __nv_bfloat16 h2 = __float2bfloat16(a2), h3 = __float2bfloat16(a3);
    __nv_bfloat16 l0 = __float2bfloat16(a0 - __bfloat162float(h0));
    __nv_bfloat16 l1 = __float2bfloat16(a1 - __bfloat162float(h1));
    __nv_bfloat16 l2 = __float2bfloat16(a2 - __bfloat162float(h2));
    __nv_bfloat16 l3 = __float2bfloat16(a3 - __bfloat162float(h3));
    size_t o = ((size_t)gm << 10) + e0;
    *(__nv_bfloat162*)(g_ahi + o) = __halves2bfloat162(h0, h1);
    *(__nv_bfloat162*)(g_ahi + o + 2) = __halves2bfloat162(h2, h3);
    *(__nv_bfloat162*)(g_alo + o) = __halves2bfloat162(l0, l1);
    *(__nv_bfloat162*)(g_alo + o + 2) = __halves2bfloat162(l2, l3);
}

// ---------------- GEMM core (mma.sync bf16) ----------------------------------
// tile 128x128, BK=64, 8 warps (warp tile 64x32), 2-stage cp.async pipeline
#define PITCH 72                   // 64 + 8 pad elems (144B rows; ldmatrix conflict-free)
#define ATILE_B (128 * PITCH * 2)  // 18432
#define STG (2 * ATILE_B)          // 36864 per stage (A + B)
#define SMEM_TOT (2 * STG)         // 73728

__device__ __forceinline__ void load_stage(uint32_t sbase,
                                           const __nv_bfloat16* __restrict__ A,
                                           const __nv_bfloat16* __restrict__ B,
                                           int m0, int n0, int k0,
                                           int ap, int bp, int tid) {
#pragma unroll
    for (int i = 0; i < 4; i++) {
        int u = i * 256 + tid;
        int row = u >> 3, c16 = u & 7;
        const void* src = A + (size_t)(m0 + row) * ap + k0 + c16 * 8;
        CP_ASYNC16(sbase + (row * PITCH + c16 * 8) * 2, src);
    }
#pragma unroll
    for (int i = 0; i < 4; i++) {
        int u = i * 256 + tid;
        int row = u >> 3, c16 = u & 7;
        const void* src = B + (size_t)(n0 + row) * bp + k0 + c16 * 8;
        CP_ASYNC16(sbase + ATILE_B + (row * PITCH + c16 * 8) * 2, src);
    }
}

__device__ __forceinline__ void compute_stage(uint32_t sA, uint32_t sB,
                                              int wm, int wn, int lane,
                                              float acc[4][4][4]) {
#pragma unroll
    for (int kk = 0; kk < 4; kk++) {
        uint32_t a[4][4];
#pragma unroll
        for (int mt = 0; mt < 4; mt++) {
            uint32_t ad = sA + ((wm * 64 + mt * 16 + (lane & 15)) * PITCH
                                + kk * 16 + (lane >> 4) * 8) * 2;
            asm volatile("ldmatrix.sync.aligned.m8n8.x4.shared.b16 {%0,%1,%2,%3}, [%4];"
                : "=r"(a[mt][0]), "=r"(a[mt][1]), "=r"(a[mt][2]), "=r"(a[mt][3]) : "r"(ad));
        }
        uint32_t b[2][4];
#pragma unroll
        for (int nb = 0; nb < 2; nb++) {
            uint32_t bd = sB + ((wn * 32 + nb * 16 + (lane & 15)) * PITCH
                                + kk * 16 + (lane >> 4) * 8) * 2;
            asm volatile("ldmatrix.sync.aligned.m8n8.x4.shared.b16 {%0,%1,%2,%3}, [%4];"
                : "=r"(b[nb][0]), "=r"(b[nb][1]), "=r"(b[nb][2]), "=r"(b[nb][3]) : "r"(bd));
        }
#pragma unroll
        for (int mt = 0; mt < 4; mt++)
#pragma unroll
            for (int nt = 0; nt < 4; nt++) {
                uint32_t b0 = b[nt >> 1][nt & 1], b1 = b[nt >> 1][2 + (nt & 1)];
                asm volatile(
                    "mma.sync.aligned.m16n8k16.row.col.f32.bf16.bf16.f32 "
                    "{%0,%1,%2,%3}, {%4,%5,%6,%7}, {%8,%9}, {%0,%1,%2,%3};"
                    : "+f"(acc[mt][nt][0]), "+f"(acc[mt][nt][1]),
                      "+f"(acc[mt][nt][2]), "+f"(acc[mt][nt][3])
                    : "r"(a[mt][0]), "r"(a[mt][1]), "r"(a[mt][2]), "r"(a[mt][3]),
                      "r"(b0), "r"(b1));
            }
    }
}

// ---------------- GEMM1: f = sin(gate+bg)*(val+bv), write bf16 hi/lo ---------
// grid (64, 2), block 256
__global__ __launch_bounds__(256) void k_gemm1(const float* __restrict__ b_up) {
    extern __shared__ char smem[];
    uint32_t sb = smem_u32(smem);
    int tid = threadIdx.x, lane = tid & 31, wid = tid >> 5;
    int wm = wid & 1, wn = wid >> 1;
    int bx = blockIdx.x, by = blockIdx.y;
    float acc[4][4][4];
#pragma unroll
    for (int i = 0; i < 4; i++)
#pragma unroll
        for (int j = 0; j < 4; j++)
#pragma unroll
            for (int k = 0; k < 4; k++) acc[i][j][k] = 0.f;

    const int C = 48;   // 3 phases x 16 chunks of 64
    {
        load_stage(sb, g_ahi, g_wuphi, by * 128, bx * 128, 0, 1024, 1024, tid);
        CP_COMMIT();
    }
    for (int c = 0; c < C; c++) {
        if (c + 1 < C) {
            int cn = c + 1;
            int p = cn >> 4, j = cn & 15;
            const __nv_bfloat16* A = (p == 1) ? g_alo : g_ahi;
            const __nv_bfloat16* B = (p == 2) ? g_wuplo : g_wuphi;
            load_stage(sb + (cn & 1) * STG, A, B, by * 128, bx * 128, j * 64, 1024, 1024, tid);
        }
        CP_COMMIT();
        CP_WAIT1();
        __syncthreads();
        uint32_t st = sb + (c & 1) * STG;
        compute_stage(st, st + ATILE_B, wm, wn, lane, acc);
        __syncthreads();
    }

#pragma unroll
    for (int mt = 0; mt < 4; mt++) {
        int r0 = by * 128 + wm * 64 + mt * 16 + (lane >> 2);
#pragma unroll
        for (int nt = 0; nt < 4; nt++) {
            int fc = bx * 64 + wn * 16 + nt * 4 + (lane & 3);
            float bg = b_up[fc], bv = b_up[4096 + fc];
            float f0 = sinf(acc[mt][nt][0] + bg) * (acc[mt][nt][1] + bv);
            float f1 = sinf(acc[mt][nt][2] + bg) * (acc[mt][nt][3] + bv);
            size_t o0 = (size_t)r0 * 4096 + fc;
            size_t o1 = o0 + (size_t)8 * 4096;
            __nv_bfloat16 h0 = __float2bfloat16(f0);
            g_fhi[o0] = h0;
            g_flo[o0] = __float2bfloat16(f0 - __bfloat162float(h0));
            __nv_bfloat16 h1 = __float2bfloat16(f1);
            g_fhi[o1] = h1;
            g_flo[o1] = __float2bfloat16(f1 - __bfloat162float(h1));
        }
    }
}

// ---------------- GEMM2: split-K=8 -> g_opart --------------------------------
// grid (8, 2, 8), block 256
__global__ __launch_bounds__(256) void k_gemm2() {
    extern __shared__ char smem[];
    uint32_t sb = smem_u32(smem);
    int tid = threadIdx.x, lane = tid & 31, wid = tid >> 5;
    int wm = wid & 1, wn = wid >> 1;
    int bx = blockIdx.x, by = blockIdx.y, bz = blockIdx.z;
    float acc[4][4][4];
#pragma unroll
    for (int i = 0; i < 4; i++)
#pragma unroll
        for (int j = 0; j < 4; j++)
#pragma unroll
            for (int k = 0; k < 4; k++) acc[i][j][k] = 0.f;

    const int C = 24;   // 3 phases x 8 chunks of 64
    {
        load_stage(sb, g_fhi, g_wdnhi, by * 128, bx * 128, bz * 512, 4096, 4096, tid);
        CP_COMMIT();
    }
    for (int c = 0; c < C; c++) {
        if (c + 1 < C) {
            int cn = c + 1;
            int p = cn >> 3, j = cn & 7;
            const __nv_bfloat16* A = (p == 1) ? g_flo : g_fhi;
            const __nv_bfloat16* B = (p == 2) ? g_wdnlo : g_wdnhi;
            load_stage(sb + (cn & 1) * STG, A, B, by * 128, bx * 128,
                       bz * 512 + j * 64, 4096, 4096, tid);
        }
        CP_COMMIT();
        CP_WAIT1();
        __syncthreads();
        uint32_t st = sb + (c & 1) * STG;
        compute_stage(st, st + ATILE_B, wm, wn, lane, acc);
        __syncthreads();
    }

#pragma unroll
    for (int mt = 0; mt < 4; mt++) {
        int r0 = by * 128 + wm * 64 + mt * 16 + (lane >> 2);
#pragma unroll
        for (int nt = 0; nt < 4; nt++) {
            int col = bx * 128 + wn * 32 + nt * 8 + (lane & 3) * 2;
            float* op = g_opart + ((size_t)(bz * 256) + r0) * 1024 + col;
            *(float2*)op = make_float2(acc[mt][nt][0], acc[mt][nt][1]);
            *(float2*)(op + (size_t)8 * 1024) = make_float2(acc[mt][nt][2], acc[mt][nt][3]);
        }
    }
}

// ---------------- step kernel 5: reduce + residual + scatter -----------------
__global__ __launch_bounds__(256) void k_fin(const float* __restrict__ b_down,
                                             float* __restrict__ out, int step) {
    int gm = blockIdx.x, tid = threadIdx.x;
    int nn = tid * 4;
    float4 a = *(const float4*)(g_opart + ((size_t)gm << 10) + nn);
#pragma unroll
    for (int s = 1; s < 8; s++) {
        float4 p = *(const float4*)(g_opart + ((size_t)((s << 8) + gm) << 10) + nn);
        a.x += p.x; a.y += p.y; a.z += p.z; a.w += p.w;
    }
    float4 bd = *(const float4*)(b_down + nn);
    float4 r2 = *(const float4*)(g_res2 + ((size_t)gm << 10) + nn);
    a.x += bd.x + r2.x; a.y += bd.y + r2.y; a.z += bd.z + r2.z; a.w += bd.w + r2.w;
    int b = gm >> 6, t = gm & 63;
    float* dst = (t < 32)
        ? out + ((size_t)(b * T_TOK + step * 32 + t) << 10) + nn
        : g_state + ((b * 32 + (t - 32)) << 10) + nn;
    *(float4*)dst = a;
}

// ---------------- host launcher ----------------------------------------------
extern "C" void kernel_launch(void* const* d_in, const int* in_sizes, int n_in,
                              void* d_out, int out_size) {
    const float* x    = (const float*)d_in[0];
    const float* ln1w = (const float*)d_in[1];
    const float* ln1b = (const float*)d_in[2];
    const float* wf1  = (const float*)d_in[3];
    const float* wf2  = (const float*)d_in[4];
    const float* ln2w = (const float*)d_in[5];
    const float* ln2b = (const float*)d_in[6];
    const float* w_up = (const float*)d_in[7];
    const float* b_up = (const float*)d_in[8];
    const float* w_dn = (const float*)d_in[9];
    const float* b_dn = (const float*)d_in[10];
    float* out = (float*)d_out;

    static int configured = 0;
    cudaFuncSetAttribute(k_gemm1, cudaFuncAttributeMaxDynamicSharedMemorySize, SMEM_TOT);
    cudaFuncSetAttribute(k_gemm2, cudaFuncAttributeMaxDynamicSharedMemorySize, SMEM_TOT);
    (void)configured;

    k_init_M<<<16, 256>>>(wf1, wf2);
    k_init_state<<<128, 256>>>(x);
    k_conv_wup<<<8192, 256>>>(w_up);
    k_conv_wdn<<<1024, 256>>>(w_dn);

    for (int i = 0; i < NSTEP; i++) {
        k_ln1<<<dim3(64, 4), 256>>>(x, ln1w, ln1b, i);
        k_fft<<<dim3(64, 4), 256>>>(x, ln2w, ln2b, i);
        k_gemm1<<<dim3(64, 2), 256, SMEM_TOT>>>(b_up);
        k_gemm2<<<dim3(8, 2, 8), 256, SMEM_TOT>>>();
        k_fin<<<256, 256>>>(b_dn, out, i);
    }
}

// round 8
// speedup vs baseline: 3.5807x; 1.0316x over previous
#include <cuda_runtime.h>
#include <cuda_bf16.h>
#include <math.h>
#include <stdint.h>

#define T_TOK 4096
#define E_DIM 1024
#define B_SZ  4
#define NSTEP 128

// ---------------- persistent device scratch ---------------------------------
__device__ float g_M[64 * 64];
__device__ float g_state[B_SZ * 32 * E_DIM];
__device__ float g_cn[B_SZ * 64 * E_DIM];
__device__ float g_res2[B_SZ * 64 * E_DIM];
__device__ __nv_bfloat16 g_ahi[256 * 1024];     // LN2 activations hi
__device__ __nv_bfloat16 g_alo[256 * 1024];     // lo residual
__device__ __nv_bfloat16 g_fhi[256 * 4096];     // sin(gate)*val hi
__device__ __nv_bfloat16 g_flo[256 * 4096];
__device__ __nv_bfloat16 g_wuphi[8192 * 1024];  // pair-interleaved w_up hi
__device__ __nv_bfloat16 g_wuplo[8192 * 1024];
__device__ __nv_bfloat16 g_wdnhi[1024 * 4096];
__device__ __nv_bfloat16 g_wdnlo[1024 * 4096];
__device__ float g_opart[8 * 256 * 1024];
__device__ int g_cnt[16];                       // split-K semaphores (zero-init)

// ---------------- helpers ----------------------------------------------------
__device__ __forceinline__ uint32_t smem_u32(const void* p) {
    uint32_t a;
    asm("{ .reg .u64 t; cvta.to.shared.u64 t, %1; cvt.u32.u64 %0, t; }" : "=r"(a) : "l"(p));
    return a;
}
#define CP_ASYNC16(dst, src) \
    asm volatile("cp.async.cg.shared.global [%0], [%1], 16;" :: "r"(dst), "l"(src))
#define CP_COMMIT() asm volatile("cp.async.commit_group;" ::: "memory")
#define CP_WAIT1()  asm volatile("cp.async.wait_group 1;" ::: "memory")

__device__ __forceinline__ float warp_sum(float v) {
#pragma unroll
    for (int m = 16; m > 0; m >>= 1) v += __shfl_xor_sync(0xffffffffu, v, m);
    return v;
}

// ---------------- init kernels -----------------------------------------------
__global__ void k_init_M(const float* __restrict__ wf1, const float* __restrict__ wf2) {
    int idx = blockIdx.x * 256 + threadIdx.x;
    int t = idx >> 6, tp = idx & 63;
    float s = 0.f;
#pragma unroll 8
    for (int u = 0; u < 48; u++) s = fmaf(wf2[t * 48 + u], wf1[u * 64 + tp], s);
    g_M[idx] = s;
}
__global__ void k_init_state(const float* __restrict__ x) {
    int idx = (blockIdx.x * 256 + threadIdx.x) * 4;
    int b = idx >> 15, r = idx & 32767;
    *(float4*)(g_state + idx) = *(const float4*)(x + ((size_t)b << 22) + r);
}
// pair-interleave: dst row n: nt=n>>7, i=n&127: even i -> gate nt*64+i/2, odd -> val
__global__ void k_conv_wup(const float* __restrict__ w) {
    int n = blockIdx.x, tid = threadIdx.x;
    int nt = n >> 7, i = n & 127;
    int src = (i & 1) ? (4096 + nt * 64 + (i >> 1)) : (nt * 64 + (i >> 1));
    const float* sp = w + ((size_t)src << 10);
    int c = tid * 4;
    float4 v = *(const float4*)(sp + c);
    __nv_bfloat16 h0 = __float2bfloat16(v.x), h1 = __float2bfloat16(v.y);
    __nv_bfloat16 h2 = __float2bfloat16(v.z), h3 = __float2bfloat16(v.w);
    __nv_bfloat16 l0 = __float2bfloat16(v.x - __bfloat162float(h0));
    __nv_bfloat16 l1 = __float2bfloat16(v.y - __bfloat162float(h1));
    __nv_bfloat16 l2 = __float2bfloat16(v.z - __bfloat162float(h2));
    __nv_bfloat16 l3 = __float2bfloat16(v.w - __bfloat162float(h3));
    size_t o = ((size_t)n << 10) + c;
    *(__nv_bfloat162*)(g_wuphi + o) = __halves2bfloat162(h0, h1);
    *(__nv_bfloat162*)(g_wuphi + o + 2) = __halves2bfloat162(h2, h3);
    *(__nv_bfloat162*)(g_wuplo + o) = __halves2bfloat162(l0, l1);
    *(__nv_bfloat162*)(g_wuplo + o + 2) = __halves2bfloat162(l2, l3);
}
__global__ void k_conv_wdn(const float* __restrict__ w) {
    int e = blockIdx.x, tid = threadIdx.x;
    const float* sp = w + (size_t)e * 4096;
#pragma unroll
    for (int j = 0; j < 4; j++) {
        int c = (j * 256 + tid) * 4;
        float4 v = *(const float4*)(sp + c);
        __nv_bfloat16 h0 = __float2bfloat16(v.x), h1 = __float2bfloat16(v.y);
        __nv_bfloat16 h2 = __float2bfloat16(v.z), h3 = __float2bfloat16(v.w);
        __nv_bfloat16 l0 = __float2bfloat16(v.x - __bfloat162float(h0));
        __nv_bfloat16 l1 = __float2bfloat16(v.y - __bfloat162float(h1));
        __nv_bfloat16 l2 = __float2bfloat16(v.z - __bfloat162float(h2));
        __nv_bfloat16 l3 = __float2bfloat16(v.w - __bfloat162float(h3));
        size_t o = (size_t)e * 4096 + c;
        *(__nv_bfloat162*)(g_wdnhi + o) = __halves2bfloat162(h0, h1);
        *(__nv_bfloat162*)(g_wdnhi + o + 2) = __halves2bfloat162(h2, h3);
        *(__nv_bfloat162*)(g_wdnlo + o) = __halves2bfloat162(l0, l1);
        *(__nv_bfloat162*)(g_wdnlo + o + 2) = __halves2bfloat162(l2, l3);
    }
}

// ---------------- step kernel 1: LN1 -> g_cn ---------------------------------
__global__ __launch_bounds__(256) void k_ln1(const float* __restrict__ x,
                                             const float* __restrict__ w,
                                             const float* __restrict__ bb, int step) {
    int t = blockIdx.x, b = blockIdx.y, tid = threadIdx.x;
    float4 vv = make_float4(0.f, 0.f, 0.f, 0.f);
    if (t < 32) {
        vv = *(const float4*)(g_state + ((b * 32 + t) << 10) + tid * 4);
    } else {
        int tok = step * 32 + t;
        if (tok < T_TOK)
            vv = *(const float4*)(x + ((size_t)(b * T_TOK + tok) << 10) + tid * 4);
    }
    float s = vv.x + vv.y + vv.z + vv.w;
    float q = vv.x * vv.x + vv.y * vv.y + vv.z * vv.z + vv.w * vv.w;
    __shared__ float rs[8], rq[8], smu, srstd;
    s = warp_sum(s); q = warp_sum(q);
    int wid = tid >> 5;
    if ((tid & 31) == 0) { rs[wid] = s; rq[wid] = q; }
    __syncthreads();
    if (tid == 0) {
        float S = 0.f, Q = 0.f;
#pragma unroll
        for (int i = 0; i < 8; i++) { S += rs[i]; Q += rq[i]; }
        float mu = S * (1.f / 1024.f);
        smu = mu;
        srstd = rsqrtf(Q * (1.f / 1024.f) - mu * mu + 1e-5f);
    }
    __syncthreads();
    float mu = smu, rstd = srstd;
    float4 wv = *(const float4*)(w + tid * 4);
    float4 bv = *(const float4*)(bb + tid * 4);
    float4 o;
    o.x = (vv.x - mu) * rstd * wv.x + bv.x;
    o.y = (vv.y - mu) * rstd * wv.y + bv.y;
    o.z = (vv.z - mu) * rstd * wv.z + bv.z;
    o.w = (vv.w - mu) * rstd * wv.w + bv.w;
    *(float4*)(g_cn + ((b * 64 + t) << 10) + tid * 4) = o;
}

// ---------------- step kernel 2: fft + res2 + LN2 + bf16-split ---------------
__global__ __launch_bounds__(256) void k_fft(const float* __restrict__ x,
                                             const float* __restrict__ ln2w,
                                             const float* __restrict__ ln2b, int step) {
    int t = blockIdx.x, b = blockIdx.y, tid = threadIdx.x;
    __shared__ float Mrow[64];
    __shared__ float rs[8], rq[8], smu, srstd;
    if (tid < 64) Mrow[tid] = g_M[t * 64 + tid];
    __syncthreads();
    int e0 = tid * 4;
    float4 acc = make_float4(0.f, 0.f, 0.f, 0.f);
    for (int tp = 0; tp <= t; tp++) {
        float m = Mrow[tp];
        float4 c = *(const float4*)(g_cn + ((b * 64 + tp) << 10) + e0);
        acc.x = fmaf(m, c.x, acc.x);
        acc.y = fmaf(m, c.y, acc.y);
        acc.z = fmaf(m, c.z, acc.z);
        acc.w = fmaf(m, c.w, acc.w);
    }
    int tok = step * 32 + t;
    if (tok < T_TOK) {
        float4 cv = *(const float4*)(x + ((size_t)(b * T_TOK + tok) << 10) + e0);
        acc.x += cv.x; acc.y += cv.y; acc.z += cv.z; acc.w += cv.w;
    }
    int gm = b * 64 + t;
    *(float4*)(g_res2 + ((size_t)gm << 10) + e0) = acc;
    float s = acc.x + acc.y + acc.z + acc.w;
    float q = acc.x * acc.x + acc.y * acc.y + acc.z * acc.z + acc.w * acc.w;
    s = warp_sum(s); q = warp_sum(q);
    int wid = tid >> 5;
    if ((tid & 31) == 0) { rs[wid] = s; rq[wid] = q; }
    __syncthreads();
    if (tid == 0) {
        float S = 0.f, Q = 0.f;
#pragma unroll
        for (int i = 0; i < 8; i++) { S += rs[i]; Q += rq[i]; }
        float mu = S * (1.f / 1024.f);
        smu = mu;
        srstd = rsqrtf(Q * (1.f / 1024.f) - mu * mu + 1e-5f);
    }
    __syncthreads();
    float mu = smu, rstd = srstd;
    float4 wv = *(const float4*)(ln2w + e0);
    float4 bv = *(const float4*)(ln2b + e0);
    float a0 = (acc.x - mu) * rstd * wv.x + bv.x;
    float a1 = (acc.y - mu) * rstd * wv.y + bv.y;
    float a2 = (acc.z - mu) * rstd * wv.z + bv.z;
    float a3 = (acc.w - mu) * rstd * wv.w + bv.w;
    __nv_bfloat16 h0 = __float2bfloat16(a0), h1 = __float2bfloat16(a1);
    __nv_bfloat16 h2 = __float2bfloat16(a2), h3 = __float2bfloat16(a3);
    __nv_bfloat16 l0 = __float2bfloat16(a0 - __bfloat162float(h0));
    __nv_bfloat16 l1 = __float2bfloat16(a1 - __bfloat162float(h1));
    __nv_bfloat16 l2 = __float2bfloat16(a2 - __bfloat162float(h2));
    __nv_bfloat16 l3 = __float2bfloat16(a3 - __bfloat162float(h3));
    size_t o = ((size_t)gm << 10) + e0;
    *(__nv_bfloat162*)(g_ahi + o) = __halves2bfloat162(h0, h1);
    *(__nv_bfloat162*)(g_ahi + o + 2) = __halves2bfloat162(h2, h3);
    *(__nv_bfloat162*)(g_alo + o) = __halves2bfloat162(l0, l1);
    *(__nv_bfloat162*)(g_alo + o + 2) = __halves2bfloat162(l2, l3);
}

// ---------------- GEMM core --------------------------------------------------
// tile 128x128, BK=64; stage = {Ahi, Alo, Bhi, Blo}; 3 mma passes per chunk
#define PITCH 72
#define TILE_B (128 * PITCH * 2)    // 18432
#define STG4 (4 * TILE_B)           // 73728 per stage
#define SMEM_TOT (2 * STG4)         // 147456

__device__ __forceinline__ void load_tile(uint32_t sbase,
                                          const __nv_bfloat16* __restrict__ P,
                                          int r0, int k0, int pitch, int tid) {
#pragma unroll
    for (int i = 0; i < 4; i++) {
        int u = i * 256 + tid;
        int row = u >> 3, c16 = u & 7;
        const void* src = P + (size_t)(r0 + row) * pitch + k0 + c16 * 8;
        CP_ASYNC16(sbase + (row * PITCH + c16 * 8) * 2, src);
    }
}
__device__ __forceinline__ void load_stage4(uint32_t sbase,
                                            const __nv_bfloat16* Ahi, const __nv_bfloat16* Alo,
                                            const __nv_bfloat16* Bhi, const __nv_bfloat16* Blo,
                                            int m0, int n0, int k0, int ap, int bp, int tid) {
    load_tile(sbase,              Ahi, m0, k0, ap, tid);
    load_tile(sbase + TILE_B,     Alo, m0, k0, ap, tid);
    load_tile(sbase + 2 * TILE_B, Bhi, n0, k0, bp, tid);
    load_tile(sbase + 3 * TILE_B, Blo, n0, k0, bp, tid);
}

#define MMA(acc, a, b0, b1) \
    asm volatile("mma.sync.aligned.m16n8k16.row.col.f32.bf16.bf16.f32 " \
        "{%0,%1,%2,%3}, {%4,%5,%6,%7}, {%8,%9}, {%0,%1,%2,%3};" \
        : "+f"((acc)[0]), "+f"((acc)[1]), "+f"((acc)[2]), "+f"((acc)[3]) \
        : "r"((a)[0]), "r"((a)[1]), "r"((a)[2]), "r"((a)[3]), "r"(b0), "r"(b1))

__device__ __forceinline__ void compute_chunk(uint32_t sbase, int wm, int wn, int lane,
                                              float acc[4][4][4]) {
    uint32_t sAhi = sbase, sAlo = sbase + TILE_B;
    uint32_t sBhi = sbase + 2 * TILE_B, sBlo = sbase + 3 * TILE_B;
#pragma unroll
    for (int kk = 0; kk < 4; kk++) {
        uint32_t ahi[4][4], alo[4][4], bhi[2][4], blo[2][4];
#pragma unroll
        for (int mt = 0; mt < 4; mt++) {
            uint32_t off = ((wm * 64 + mt * 16 + (lane & 15)) * PITCH
                            + kk * 16 + (lane >> 4) * 8) * 2;
            asm volatile("ldmatrix.sync.aligned.m8n8.x4.shared.b16 {%0,%1,%2,%3}, [%4];"
                : "=r"(ahi[mt][0]), "=r"(ahi[mt][1]), "=r"(ahi[mt][2]), "=r"(ahi[mt][3])
                : "r"(sAhi + off));
            asm volatile("ldmatrix.sync.aligned.m8n8.x4.shared.b16 {%0,%1,%2,%3}, [%4];"
                : "=r"(alo[mt][0]), "=r"(alo[mt][1]), "=r"(alo[mt][2]), "=r"(alo[mt][3])
                : "r"(sAlo + off));
        }
#pragma unroll
        for (int nb = 0; nb < 2; nb++) {
            uint32_t off = ((wn * 32 + nb * 16 + (lane & 15)) * PITCH
                            + kk * 16 + (lane >> 4) * 8) * 2;
            asm volatile("ldmatrix.sync.aligned.m8n8.x4.shared.b16 {%0,%1,%2,%3}, [%4];"
                : "=r"(bhi[nb][0]), "=r"(bhi[nb][1]), "=r"(bhi[nb][2]), "=r"(bhi[nb][3])
                : "r"(sBhi + off));
            asm volatile("ldmatrix.sync.aligned.m8n8.x4.shared.b16 {%0,%1,%2,%3}, [%4];"
                : "=r"(blo[nb][0]), "=r"(blo[nb][1]), "=r"(blo[nb][2]), "=r"(blo[nb][3])
                : "r"(sBlo + off));
        }
#pragma unroll
        for (int mt = 0; mt < 4; mt++)
#pragma unroll
            for (int nt = 0; nt < 4; nt++) {
                int hb = nt >> 1, lb = nt & 1;
                MMA(acc[mt][nt], ahi[mt], bhi[hb][lb], bhi[hb][2 + lb]);
                MMA(acc[mt][nt], alo[mt], bhi[hb][lb], bhi[hb][2 + lb]);
                MMA(acc[mt][nt], ahi[mt], blo[hb][lb], blo[hb][2 + lb]);
            }
    }
}

// ---------------- GEMM1 ------------------------------------------------------
// grid (64, 2), block 256
__global__ __launch_bounds__(256) void k_gemm1(const float* __restrict__ b_up) {
    extern __shared__ char smem[];
    uint32_t sb = smem_u32(smem);
    int tid = threadIdx.x, lane = tid & 31, wid = tid >> 5;
    int wm = wid & 1, wn = wid >> 1;
    int bx = blockIdx.x, by = blockIdx.y;
    float acc[4][4][4];
#pragma unroll
    for (int i = 0; i < 4; i++)
#pragma unroll
        for (int j = 0; j < 4; j++)
#pragma unroll
            for (int k = 0; k < 4; k++) acc[i][j][k] = 0.f;

    const int C = 16;
    load_stage4(sb, g_ahi, g_alo, g_wuphi, g_wuplo, by * 128, bx * 128, 0, 1024, 1024, tid);
    CP_COMMIT();
    for (int c = 0; c < C; c++) {
        if (c + 1 < C)
            load_stage4(sb + ((c + 1) & 1) * STG4, g_ahi, g_alo, g_wuphi, g_wuplo,
                        by * 128, bx * 128, (c + 1) * 64, 1024, 1024, tid);
        CP_COMMIT();
        CP_WAIT1();
        __syncthreads();
        compute_chunk(sb + (c & 1) * STG4, wm, wn, lane, acc);
        __syncthreads();
    }

#pragma unroll
    for (int mt = 0; mt < 4; mt++) {
        int r0 = by * 128 + wm * 64 + mt * 16 + (lane >> 2);
#pragma unroll
        for (int nt = 0; nt < 4; nt++) {
            int fc = bx * 64 + wn * 16 + nt * 4 + (lane & 3);
            float bg = b_up[fc], bv = b_up[4096 + fc];
            float f0 = sinf(acc[mt][nt][0] + bg) * (acc[mt][nt][1] + bv);
            float f1 = sinf(acc[mt][nt][2] + bg) * (acc[mt][nt][3] + bv);
            size_t o0 = (size_t)r0 * 4096 + fc;
            size_t o1 = o0 + (size_t)8 * 4096;
            __nv_bfloat16 h0 = __float2bfloat16(f0);
            g_fhi[o0] = h0;
            g_flo[o0] = __float2bfloat16(f0 - __bfloat162float(h0));
            __nv_bfloat16 h1 = __float2bfloat16(f1);
            g_fhi[o1] = h1;
            g_flo[o1] = __float2bfloat16(f1 - __bfloat162float(h1));
        }
    }
}

// ---------------- GEMM2 + fused split-K finisher -----------------------------
// grid (8, 2, 8), block 256
__global__ __launch_bounds__(256) void k_gemm2(const float* __restrict__ b_down,
                                               float* __restrict__ out, int step) {
    extern __shared__ char smem[];
    uint32_t sb = smem_u32(smem);
    int tid = threadIdx.x, lane = tid & 31, wid = tid >> 5;
    int wm = wid & 1, wn = wid >> 1;
    int bx = blockIdx.x, by = blockIdx.y, bz = blockIdx.z;
    float acc[4][4][4];
#pragma unroll
    for (int i = 0; i < 4; i++)
#pragma unroll
        for (int j = 0; j < 4; j++)
#pragma unroll
            for (int k = 0; k < 4; k++) acc[i][j][k] = 0.f;

    const int C = 8;
    load_stage4(sb, g_fhi, g_flo, g_wdnhi, g_wdnlo,
                by * 128, bx * 128, bz * 512, 4096, 4096, tid);
    CP_COMMIT();
    for (int c = 0; c < C; c++) {
        if (c + 1 < C)
            load_stage4(sb + ((c + 1) & 1) * STG4, g_fhi, g_flo, g_wdnhi, g_wdnlo,
                        by * 128, bx * 128, bz * 512 + (c + 1) * 64, 4096, 4096, tid);
        CP_COMMIT();
        CP_WAIT1();
        __syncthreads();
        compute_chunk(sb + (c & 1) * STG4, wm, wn, lane, acc);
        __syncthreads();
    }

#pragma unroll
    for (int mt = 0; mt < 4; mt++) {
        int r0 = by * 128 + wm * 64 + mt * 16 + (lane >> 2);
#pragma unroll
        for (int nt = 0; nt < 4; nt++) {
            int col = bx * 128 + wn * 32 + nt * 8 + (lane & 3) * 2;
            float* op = g_opart + ((size_t)(bz * 256) + r0) * 1024 + col;
            *(float2*)op = make_float2(acc[mt][nt][0], acc[mt][nt][1]);
            *(float2*)(op + (size_t)8 * 1024) = make_float2(acc[mt][nt][2], acc[mt][nt][3]);
        }
    }

    // ---- split-K finisher: 8th-arriving CTA per (bx,by) reduces ----
    __threadfence();   // release our g_opart stores
    __shared__ int s_last;
    if (tid == 0) {
        int old;
        asm volatile("atom.add.release.gpu.s32 %0, [%1], 1;"
                     : "=r"(old) : "l"(&g_cnt[by * 8 + bx]) : "memory");
        s_last = (old == 7);
    }
    __syncthreads();
    if (s_last) {
        __threadfence();   // acquire: observe all 8 CTAs' partials
#pragma unroll
        for (int i = 0; i < 16; i++) {
            int u = i * 256 + tid;            // 4096 float4 slots
            int r = u >> 5, c4 = (u & 31) * 4;
            int gm = by * 128 + r;
            int col = bx * 128 + c4;
            float4 a = *(const float4*)(g_opart + ((size_t)gm << 10) + col);
#pragma unroll
            for (int s = 1; s < 8; s++) {
                float4 p = *(const float4*)(g_opart + ((size_t)((s << 8) + gm) << 10) + col);
                a.x += p.x; a.y += p.y; a.z += p.z; a.w += p.w;
            }
            float4 bd = *(const float4*)(b_down + col);
            float4 r2 = *(const float4*)(g_res2 + ((size_t)gm << 10) + col);
            a.x += bd.x + r2.x; a.y += bd.y + r2.y;
            a.z += bd.z + r2.z; a.w += bd.w + r2.w;
            int b = gm >> 6, t = gm & 63;
            float* dst = (t < 32)
                ? out + ((size_t)(b * T_TOK + step * 32 + t) << 10) + col
                : g_state + ((b * 32 + (t - 32)) << 10) + col;
            *(float4*)dst = a;
        }
        __syncthreads();
        if (tid == 0) g_cnt[by * 8 + bx] = 0;
    }
}

// ---------------- host launcher ----------------------------------------------
extern "C" void kernel_launch(void* const* d_in, const int* in_sizes, int n_in,
                              void* d_out, int out_size) {
    const float* x    = (const float*)d_in[0];
    const float* ln1w = (const float*)d_in[1];
    const float* ln1b = (const float*)d_in[2];
    const float* wf1  = (const float*)d_in[3];
    const float* wf2  = (const float*)d_in[4];
    const float* ln2w = (const float*)d_in[5];
    const float* ln2b = (const float*)d_in[6];
    const float* w_up = (const float*)d_in[7];
    const float* b_up = (const float*)d_in[8];
    const float* w_dn = (const float*)d_in[9];
    const float* b_dn = (const float*)d_in[10];
    float* out = (float*)d_out;

    cudaFuncSetAttribute(k_gemm1, cudaFuncAttributeMaxDynamicSharedMemorySize, SMEM_TOT);
    cudaFuncSetAttribute(k_gemm2, cudaFuncAttributeMaxDynamicSharedMemorySize, SMEM_TOT);

    k_init_M<<<16, 256>>>(wf1, wf2);
    k_init_state<<<128, 256>>>(x);
    k_conv_wup<<<8192, 256>>>(w_up);
    k_conv_wdn<<<1024, 256>>>(w_dn);

    for (int i = 0; i < NSTEP; i++) {
        k_ln1<<<dim3(64, 4), 256>>>(x, ln1w, ln1b, i);
        k_fft<<<dim3(64, 4), 256>>>(x, ln2w, ln2b, i);
        k_gemm1<<<dim3(64, 2), 256, SMEM_TOT>>>(b_up);
        k_gemm2<<<dim3(8, 2, 8), 256, SMEM_TOT>>>(b_dn, out, i);
    }
}